// round 1
// baseline (speedup 1.0000x reference)
#include <cuda_runtime.h>

// Problem constants (fixed by the dataset)
#define SQ   2048
#define BB   2
#define EE   1024
#define HH   16
#define DD   64
#define MM   (SQ * BB)      // 4096 rows in the GEMMs
#define BAND 128

// Scratch (device globals — no allocation allowed)
__device__ float g_q[BB * HH * SQ * DD];    // [B,H,S,D]
__device__ float g_k[BB * HH * SQ * DD];
__device__ float g_v[BB * HH * SQ * DD];
__device__ float g_ctx[SQ * BB * EE];       // [S,B,E]

// ---------------------------------------------------------------------------
// Fused QKV projection GEMM.
// grid = (M/128, 3E/128) = (32, 24), block = 256 threads, 8x8 per thread.
// C[m][n] = A[m][:] . W[n][:] + bias[n]  with A chosen by n-range,
// scattered into g_q/g_k/g_v in [B,H,S,D] layout; q scaled by 1/sqrt(D).
// ---------------------------------------------------------------------------
__global__ __launch_bounds__(256) void qkv_gemm_kernel(
    const float* __restrict__ q_in, const float* __restrict__ k_in,
    const float* __restrict__ v_in, const float* __restrict__ w,
    const float* __restrict__ bias)
{
    __shared__ float As[16][128];
    __shared__ float Bs[16][128];

    const int m0 = blockIdx.x * 128;
    const int n0 = blockIdx.y * 128;
    const int which = n0 >> 10;  // 0=q, 1=k, 2=v
    const float* __restrict__ A = (which == 0) ? q_in : (which == 1) ? k_in : v_in;

    const int tid = threadIdx.x;
    const int tx = tid & 15;
    const int ty = tid >> 4;

    float acc[8][8];
#pragma unroll
    for (int i = 0; i < 8; i++)
#pragma unroll
        for (int j = 0; j < 8; j++) acc[i][j] = 0.0f;

    for (int k0 = 0; k0 < EE; k0 += 16) {
        // Cooperative tile loads (float4), stored k-major for the inner loop.
#pragma unroll
        for (int u = 0; u < 2; u++) {
            int idx = tid * 2 + u;          // 0..511
            int r   = idx >> 2;             // tile row 0..127
            int c4  = (idx & 3) << 2;       // k offset 0,4,8,12
            float4 av = *reinterpret_cast<const float4*>(&A[(size_t)(m0 + r) * EE + k0 + c4]);
            As[c4 + 0][r] = av.x; As[c4 + 1][r] = av.y;
            As[c4 + 2][r] = av.z; As[c4 + 3][r] = av.w;
            float4 wv = *reinterpret_cast<const float4*>(&w[(size_t)(n0 + r) * EE + k0 + c4]);
            Bs[c4 + 0][r] = wv.x; Bs[c4 + 1][r] = wv.y;
            Bs[c4 + 2][r] = wv.z; Bs[c4 + 3][r] = wv.w;
        }
        __syncthreads();

#pragma unroll
        for (int kk = 0; kk < 16; kk++) {
            float a[8], b[8];
            *reinterpret_cast<float4*>(&a[0]) = *reinterpret_cast<float4*>(&As[kk][ty * 8]);
            *reinterpret_cast<float4*>(&a[4]) = *reinterpret_cast<float4*>(&As[kk][ty * 8 + 4]);
            *reinterpret_cast<float4*>(&b[0]) = *reinterpret_cast<float4*>(&Bs[kk][tx * 8]);
            *reinterpret_cast<float4*>(&b[4]) = *reinterpret_cast<float4*>(&Bs[kk][tx * 8 + 4]);
#pragma unroll
            for (int i = 0; i < 8; i++)
#pragma unroll
                for (int j = 0; j < 8; j++)
                    acc[i][j] = fmaf(a[i], b[j], acc[i][j]);
        }
        __syncthreads();
    }

    // Epilogue: scatter into [B,H,S,D] with bias and optional 1/sqrt(D) scale.
    const float scale = (which == 0) ? 0.125f : 1.0f;
    float* __restrict__ dst = (which == 0) ? g_q : (which == 1) ? g_k : g_v;
#pragma unroll
    for (int i = 0; i < 8; i++) {
        int m = m0 + ty * 8 + i;
        int s = m >> 1;          // B = 2
        int b = m & 1;
#pragma unroll
        for (int j = 0; j < 8; j++) {
            int n  = n0 + tx * 8 + j;
            int nl = n & 1023;
            int h  = nl >> 6;
            int d  = nl & 63;
            float val = (acc[i][j] + bias[n]) * scale;
            dst[(((size_t)(b * HH + h) * SQ + s) * DD) + d] = val;
        }
    }
}

// ---------------------------------------------------------------------------
// Banded flash attention.
// grid = (S/128, B*H) = (16, 32), block = 128 threads (1 thread = 1 query row).
// Only key tiles t-1, t, t+1 intersect the band. Online softmax per row.
// Dynamic smem: K tile (32KB) + V tile (32KB) + score buffer (66KB).
// ---------------------------------------------------------------------------
__global__ __launch_bounds__(128) void attn_kernel()
{
    extern __shared__ float sm[];
    float* Ks = sm;                   // [128][64]
    float* Vs = sm + 128 * 64;        // [128][64]
    float* Sc = sm + 2 * 128 * 64;    // [128][129] padded

    const int t   = blockIdx.x;
    const int bh  = blockIdx.y;       // b*H + h
    const int tid = threadIdx.x;
    const int i   = t * 128 + tid;    // global query index

    // Load this thread's q row into registers.
    const float* __restrict__ qrow = g_q + ((size_t)bh * SQ + i) * DD;
    float q[DD];
#pragma unroll
    for (int u = 0; u < DD / 4; u++)
        *reinterpret_cast<float4*>(&q[u * 4]) =
            *reinterpret_cast<const float4*>(&qrow[u * 4]);

    float m_run = -1e30f;
    float l_run = 0.0f;
    float acc[DD];
#pragma unroll
    for (int d = 0; d < DD; d++) acc[d] = 0.0f;

    for (int dt = -1; dt <= 1; dt++) {
        int kt = t + dt;
        if (kt < 0 || kt >= SQ / 128) continue;

        __syncthreads();  // previous iteration's smem reads must complete
        const float* __restrict__ kbase = g_k + ((size_t)bh * SQ + kt * 128) * DD;
        const float* __restrict__ vbase = g_v + ((size_t)bh * SQ + kt * 128) * DD;
#pragma unroll
        for (int u = 0; u < 16; u++) {
            int idx = tid + u * 128;  // float4 index, 0..2047
            *reinterpret_cast<float4*>(&Ks[idx * 4]) =
                *reinterpret_cast<const float4*>(&kbase[idx * 4]);
            *reinterpret_cast<float4*>(&Vs[idx * 4]) =
                *reinterpret_cast<const float4*>(&vbase[idx * 4]);
        }
        __syncthreads();

        // Pass 1: scores for this row over all 128 keys in the tile.
        float tmax = -1e30f;
        const int jg0 = kt * 128;
        for (int j = 0; j < 128; j++) {
            const float* __restrict__ kr = &Ks[j * DD];
            float d0 = 0.f, d1 = 0.f, d2 = 0.f, d3 = 0.f;
#pragma unroll
            for (int d = 0; d < DD; d += 4) {
                float4 kv = *reinterpret_cast<const float4*>(&kr[d]);
                d0 = fmaf(q[d + 0], kv.x, d0);
                d1 = fmaf(q[d + 1], kv.y, d1);
                d2 = fmaf(q[d + 2], kv.z, d2);
                d3 = fmaf(q[d + 3], kv.w, d3);
            }
            float dot = (d0 + d1) + (d2 + d3);
            int jg = jg0 + j;
            bool allowed = (jg >= i - BAND) && (jg < i + BAND);
            float sc = allowed ? dot : -1e30f;
            Sc[tid * 129 + j] = sc;
            tmax = fmaxf(tmax, sc);
        }

        float m_new = fmaxf(m_run, tmax);
        float corr  = __expf(m_run - m_new);
        l_run *= corr;
#pragma unroll
        for (int d = 0; d < DD; d++) acc[d] *= corr;
        m_run = m_new;

        // Pass 2: p = exp(s - m), accumulate p*V.
        for (int j = 0; j < 128; j++) {
            float p = __expf(Sc[tid * 129 + j] - m_new);
            l_run += p;
            const float* __restrict__ vr = &Vs[j * DD];
#pragma unroll
            for (int d = 0; d < DD; d += 4) {
                float4 vv = *reinterpret_cast<const float4*>(&vr[d]);
                acc[d + 0] = fmaf(p, vv.x, acc[d + 0]);
                acc[d + 1] = fmaf(p, vv.y, acc[d + 1]);
                acc[d + 2] = fmaf(p, vv.z, acc[d + 2]);
                acc[d + 3] = fmaf(p, vv.w, acc[d + 3]);
            }
        }
    }

    // Normalize and write ctx in [S,B,E] layout.
    const float inv = 1.0f / l_run;
    const int b = bh >> 4;
    const int h = bh & 15;
    float* __restrict__ crow = g_ctx + ((size_t)i * BB + b) * EE + h * DD;
#pragma unroll
    for (int u = 0; u < DD / 4; u++) {
        float4 o;
        o.x = acc[u * 4 + 0] * inv;
        o.y = acc[u * 4 + 1] * inv;
        o.z = acc[u * 4 + 2] * inv;
        o.w = acc[u * 4 + 3] * inv;
        *reinterpret_cast<float4*>(&crow[u * 4]) = o;
    }
}

// ---------------------------------------------------------------------------
// Output projection GEMM. grid = (32, 8), block = 256, same tiling as QKV.
// out[m][n] = ctx[m][:] . Wo[n][:] + bo[n]
// ---------------------------------------------------------------------------
__global__ __launch_bounds__(256) void out_gemm_kernel(
    const float* __restrict__ w, const float* __restrict__ bias,
    float* __restrict__ out)
{
    __shared__ float As[16][128];
    __shared__ float Bs[16][128];

    const int m0 = blockIdx.x * 128;
    const int n0 = blockIdx.y * 128;
    const int tid = threadIdx.x;
    const int tx = tid & 15;
    const int ty = tid >> 4;
    const float* __restrict__ A = g_ctx;

    float acc[8][8];
#pragma unroll
    for (int i = 0; i < 8; i++)
#pragma unroll
        for (int j = 0; j < 8; j++) acc[i][j] = 0.0f;

    for (int k0 = 0; k0 < EE; k0 += 16) {
#pragma unroll
        for (int u = 0; u < 2; u++) {
            int idx = tid * 2 + u;
            int r   = idx >> 2;
            int c4  = (idx & 3) << 2;
            float4 av = *reinterpret_cast<const float4*>(&A[(size_t)(m0 + r) * EE + k0 + c4]);
            As[c4 + 0][r] = av.x; As[c4 + 1][r] = av.y;
            As[c4 + 2][r] = av.z; As[c4 + 3][r] = av.w;
            float4 wv = *reinterpret_cast<const float4*>(&w[(size_t)(n0 + r) * EE + k0 + c4]);
            Bs[c4 + 0][r] = wv.x; Bs[c4 + 1][r] = wv.y;
            Bs[c4 + 2][r] = wv.z; Bs[c4 + 3][r] = wv.w;
        }
        __syncthreads();

#pragma unroll
        for (int kk = 0; kk < 16; kk++) {
            float a[8], b[8];
            *reinterpret_cast<float4*>(&a[0]) = *reinterpret_cast<float4*>(&As[kk][ty * 8]);
            *reinterpret_cast<float4*>(&a[4]) = *reinterpret_cast<float4*>(&As[kk][ty * 8 + 4]);
            *reinterpret_cast<float4*>(&b[0]) = *reinterpret_cast<float4*>(&Bs[kk][tx * 8]);
            *reinterpret_cast<float4*>(&b[4]) = *reinterpret_cast<float4*>(&Bs[kk][tx * 8 + 4]);
#pragma unroll
            for (int i = 0; i < 8; i++)
#pragma unroll
                for (int j = 0; j < 8; j++)
                    acc[i][j] = fmaf(a[i], b[j], acc[i][j]);
        }
        __syncthreads();
    }

#pragma unroll
    for (int i = 0; i < 8; i++) {
        int m = m0 + ty * 8 + i;
#pragma unroll
        for (int j = 0; j < 8; j++) {
            int n = n0 + tx * 8 + j;
            out[(size_t)m * EE + n] = acc[i][j] + bias[n];
        }
    }
}

// ---------------------------------------------------------------------------
extern "C" void kernel_launch(void* const* d_in, const int* in_sizes, int n_in,
                              void* d_out, int out_size)
{
    const float* q_in  = (const float*)d_in[0];
    const float* k_in  = (const float*)d_in[1];
    const float* v_in  = (const float*)d_in[2];
    const float* w_in  = (const float*)d_in[3];  // [3E, E]
    const float* b_in  = (const float*)d_in[4];  // [3E]
    const float* w_out = (const float*)d_in[5];  // [E, E]
    const float* b_out = (const float*)d_in[6];  // [E]
    float* out = (float*)d_out;

    // QKV projection: 768 blocks
    qkv_gemm_kernel<<<dim3(MM / 128, (3 * EE) / 128), 256>>>(q_in, k_in, v_in, w_in, b_in);

    // Banded attention: needs 128.5KB dynamic smem
    size_t smem = (size_t)(2 * 128 * 64 + 128 * 129) * sizeof(float);
    cudaFuncSetAttribute(attn_kernel, cudaFuncAttributeMaxDynamicSharedMemorySize, (int)smem);
    attn_kernel<<<dim3(SQ / 128, BB * HH), 128, smem>>>();

    // Output projection: 256 blocks, writes d_out
    out_gemm_kernel<<<dim3(MM / 128, EE / 128), 256>>>(w_out, b_out, out);
}

// round 3
// speedup vs baseline: 2.0351x; 2.0351x over previous
#include <cuda_runtime.h>
#include <cuda_bf16.h>
#include <cstdint>

// Problem constants
#define SQ   2048
#define BB   2
#define EE   1024
#define HH   16
#define DD   64
#define MM   (SQ * BB)
#define BAND 128
#define BK   32
#define NSTAGE (EE / BK)        // 32
#define LDSTRIDE 40             // halfs per smem row (80B, conflict-free ldmatrix)

// ---------------------------------------------------------------------------
// Scratch (device globals — no allocation allowed)
// ---------------------------------------------------------------------------
__device__ float g_q[BB * HH * SQ * DD];    // [B,H,S,D]
__device__ float g_k[BB * HH * SQ * DD];
__device__ float g_v[BB * HH * SQ * DD];
__device__ float g_ctx[SQ * BB * EE];       // [S,B,E]

__device__ __nv_bfloat16 g_ah[3u * MM * EE];   // q,k,v inputs hi (concatenated)
__device__ __nv_bfloat16 g_al[3u * MM * EE];   // lo
__device__ __nv_bfloat16 g_wh[3u * EE * EE];   // in_proj_w hi
__device__ __nv_bfloat16 g_wl[3u * EE * EE];
__device__ __nv_bfloat16 g_ch[(size_t)MM * EE];  // ctx hi
__device__ __nv_bfloat16 g_cl[(size_t)MM * EE];
__device__ __nv_bfloat16 g_woh[(size_t)EE * EE]; // out_proj_w hi
__device__ __nv_bfloat16 g_wol[(size_t)EE * EE];

// ---------------------------------------------------------------------------
// PTX helpers (portable sm_80+ features only — harness targets plain sm_103)
// ---------------------------------------------------------------------------
__device__ __forceinline__ uint32_t smem_u32(const void* p) {
    uint32_t a;
    asm("{ .reg .u64 t; cvta.to.shared.u64 t, %1; cvt.u32.u64 %0, t; }"
        : "=r"(a) : "l"(p));
    return a;
}

#define CP_ASYNC16(saddr, gaddr) \
    asm volatile("cp.async.cg.shared.global [%0], [%1], 16;" \
                 :: "r"(saddr), "l"(gaddr) : "memory")
#define CP_COMMIT() asm volatile("cp.async.commit_group;" ::: "memory")
#define CP_WAIT(n)  asm volatile("cp.async.wait_group %0;" :: "n"(n) : "memory")

__device__ __forceinline__ void ldsm_x4(uint32_t* r, uint32_t addr) {
    asm volatile("ldmatrix.sync.aligned.m8n8.x4.shared.b16 {%0,%1,%2,%3}, [%4];"
                 : "=r"(r[0]), "=r"(r[1]), "=r"(r[2]), "=r"(r[3]) : "r"(addr));
}
__device__ __forceinline__ void ldsm_x2(uint32_t* r, uint32_t addr) {
    asm volatile("ldmatrix.sync.aligned.m8n8.x2.shared.b16 {%0,%1}, [%2];"
                 : "=r"(r[0]), "=r"(r[1]) : "r"(addr));
}
__device__ __forceinline__ void mma_bf16(float* d, const uint32_t* a, const uint32_t* b) {
    asm volatile("mma.sync.aligned.m16n8k16.row.col.f32.bf16.bf16.f32 "
                 "{%0,%1,%2,%3}, {%4,%5,%6,%7}, {%8,%9}, {%0,%1,%2,%3};"
                 : "+f"(d[0]), "+f"(d[1]), "+f"(d[2]), "+f"(d[3])
                 : "r"(a[0]), "r"(a[1]), "r"(a[2]), "r"(a[3]), "r"(b[0]), "r"(b[1]));
}

// ---------------------------------------------------------------------------
// fp32 -> (hi, lo) bf16 split conversion. n4 = element count / 4.
// ---------------------------------------------------------------------------
__global__ __launch_bounds__(256) void cvt_kernel(
    const float4* __restrict__ src, uint2* __restrict__ hi, uint2* __restrict__ lo, int n4)
{
    int i = blockIdx.x * 256 + threadIdx.x;
    if (i >= n4) return;
    float4 v = src[i];
    __nv_bfloat16 h0 = __float2bfloat16(v.x);
    __nv_bfloat16 h1 = __float2bfloat16(v.y);
    __nv_bfloat16 h2 = __float2bfloat16(v.z);
    __nv_bfloat16 h3 = __float2bfloat16(v.w);
    __nv_bfloat16 l0 = __float2bfloat16(v.x - __bfloat162float(h0));
    __nv_bfloat16 l1 = __float2bfloat16(v.y - __bfloat162float(h1));
    __nv_bfloat16 l2 = __float2bfloat16(v.z - __bfloat162float(h2));
    __nv_bfloat16 l3 = __float2bfloat16(v.w - __bfloat162float(h3));
    uint2 H, L;
    H.x = ((uint32_t)__bfloat16_as_ushort(h1) << 16) | __bfloat16_as_ushort(h0);
    H.y = ((uint32_t)__bfloat16_as_ushort(h3) << 16) | __bfloat16_as_ushort(h2);
    L.x = ((uint32_t)__bfloat16_as_ushort(l1) << 16) | __bfloat16_as_ushort(l0);
    L.y = ((uint32_t)__bfloat16_as_ushort(l3) << 16) | __bfloat16_as_ushort(l2);
    hi[i] = H;
    lo[i] = L;
}

// ---------------------------------------------------------------------------
// Split-bf16 GEMM on mma.sync (HMMA tensor pipe).
// C[m][n] = A[m][:] . W[n][:] + bias[n]   (3 passes: AhBh + AhBl + AlBh)
// Tile 128x128, BK=32, cp.async double buffer, 8 warps (2M x 4N of 64x32).
//   mode 0: A slice by which=n0>>10 (q/k/v), scatter to g_q/g_k/g_v [B,H,S,D],
//           q scaled 1/8.
//   mode 1: write outp [M, E].
// Dynamic smem: 2 stages x 4 matrices x 128 rows x 40 halfs = 81920 B.
// ---------------------------------------------------------------------------
__global__ __launch_bounds__(256) void mma_gemm_kernel(
    const __nv_bfloat16* __restrict__ ah, const __nv_bfloat16* __restrict__ al,
    const __nv_bfloat16* __restrict__ wh, const __nv_bfloat16* __restrict__ wl,
    const float* __restrict__ bias, int mode, float* __restrict__ outp)
{
    extern __shared__ __align__(128) __nv_bfloat16 sm_[];
    const uint32_t sb = smem_u32(sm_);
    const int tid  = threadIdx.x;
    const int wid  = tid >> 5;
    const int lane = tid & 31;
    const int m0 = blockIdx.x * 128;
    const int n0 = blockIdx.y * 128;

    int which = 0;
    const __nv_bfloat16* __restrict__ Ah = ah;
    const __nv_bfloat16* __restrict__ Al = al;
    if (mode == 0) {
        which = n0 >> 10;
        Ah = ah + (size_t)which * MM * EE;
        Al = al + (size_t)which * MM * EE;
    }

    const int warp_m = (wid & 1) * 64;
    const int warp_n = (wid >> 1) * 32;

    float acc[4][4][4];
#pragma unroll
    for (int mi = 0; mi < 4; mi++)
#pragma unroll
        for (int ni = 0; ni < 4; ni++)
#pragma unroll
            for (int r = 0; r < 4; r++) acc[mi][ni][r] = 0.0f;

    // Per-stage byte offsets inside one buffer (halfs *2):
    //   Ah: 0, Al: 10240, Bh: 20480, Bl: 30720; buffer stride 40960 B.
    const int ld_row = tid >> 1;          // 0..127  (2 threads per row)
    const int ld_c4  = (tid & 1) * 2;     // uint4 index 0 or 2 (each thread: 2 consecutive)
    const uint32_t s_off = (uint32_t)(ld_row * LDSTRIDE + ld_c4 * 8) * 2;

    auto issue_stage = [&](int s) {
        const int k0 = s * BK;
        const uint32_t sbase = sb + (uint32_t)(s & 1) * 40960u;
        const __nv_bfloat16* gAh = Ah + (size_t)(m0 + ld_row) * EE + k0 + ld_c4 * 8;
        const __nv_bfloat16* gAl = Al + (size_t)(m0 + ld_row) * EE + k0 + ld_c4 * 8;
        const __nv_bfloat16* gBh = wh + (size_t)(n0 + ld_row) * EE + k0 + ld_c4 * 8;
        const __nv_bfloat16* gBl = wl + (size_t)(n0 + ld_row) * EE + k0 + ld_c4 * 8;
#pragma unroll
        for (int u = 0; u < 2; u++) {
            uint32_t so = s_off + u * 16;
            CP_ASYNC16(sbase + so,          gAh + u * 8);
            CP_ASYNC16(sbase + 10240 + so,  gAl + u * 8);
            CP_ASYNC16(sbase + 20480 + so,  gBh + u * 8);
            CP_ASYNC16(sbase + 30720 + so,  gBl + u * 8);
        }
        CP_COMMIT();
    };

    issue_stage(0);

    for (int s = 0; s < NSTAGE; s++) {
        if (s + 1 < NSTAGE) {
            issue_stage(s + 1);
            CP_WAIT(1);
        } else {
            CP_WAIT(0);
        }
        __syncthreads();

        const uint32_t sbase = sb + (uint32_t)(s & 1) * 40960u;
#pragma unroll
        for (int kk = 0; kk < 2; kk++) {
            uint32_t a_h[4][4], a_l[4][4], b_h[4][2], b_l[4][2];
#pragma unroll
            for (int mi = 0; mi < 4; mi++) {
                uint32_t off = ((uint32_t)((warp_m + mi * 16 + (lane & 15)) * LDSTRIDE
                               + ((lane >> 4) * 8) + kk * 16)) * 2;
                ldsm_x4(a_h[mi], sbase + off);
                ldsm_x4(a_l[mi], sbase + 10240 + off);
            }
#pragma unroll
            for (int ni = 0; ni < 4; ni++) {
                uint32_t off = ((uint32_t)((warp_n + ni * 8 + (lane & 7)) * LDSTRIDE
                               + (((lane >> 3) & 1) * 8) + kk * 16)) * 2;
                ldsm_x2(b_h[ni], sbase + 20480 + off);
                ldsm_x2(b_l[ni], sbase + 30720 + off);
            }
#pragma unroll
            for (int mi = 0; mi < 4; mi++)
#pragma unroll
                for (int ni = 0; ni < 4; ni++) {
                    mma_bf16(acc[mi][ni], a_h[mi], b_h[ni]);
                    mma_bf16(acc[mi][ni], a_h[mi], b_l[ni]);
                    mma_bf16(acc[mi][ni], a_l[mi], b_h[ni]);
                }
        }
        __syncthreads();
    }

    // Epilogue
    const int row_in = lane >> 2;          // 0..7
    const int col2   = (lane & 3) * 2;
    const float scale = (mode == 0 && which == 0) ? 0.125f : 1.0f;
    float* dstbase = nullptr;
    if (mode == 0) dstbase = (which == 0) ? g_q : (which == 1) ? g_k : g_v;

#pragma unroll
    for (int mi = 0; mi < 4; mi++) {
        const int m1 = m0 + warp_m + mi * 16 + row_in;
        const int m2 = m1 + 8;
#pragma unroll
        for (int ni = 0; ni < 4; ni++) {
            const int n = n0 + warp_n + ni * 8 + col2;
            const float b0 = bias[n], b1 = bias[n + 1];
            float v00 = (acc[mi][ni][0] + b0) * scale;
            float v01 = (acc[mi][ni][1] + b1) * scale;
            float v10 = (acc[mi][ni][2] + b0) * scale;
            float v11 = (acc[mi][ni][3] + b1) * scale;
            if (mode == 1) {
                *(float2*)&outp[(size_t)m1 * EE + n] = make_float2(v00, v01);
                *(float2*)&outp[(size_t)m2 * EE + n] = make_float2(v10, v11);
            } else {
                const int nl = n & 1023;
                const int h  = nl >> 6;
                const int d  = nl & 63;
                {
                    const int s_ = m1 >> 1, b_ = m1 & 1;
                    *(float2*)&dstbase[(((size_t)(b_ * HH + h) * SQ + s_) * DD) + d] =
                        make_float2(v00, v01);
                }
                {
                    const int s_ = m2 >> 1, b_ = m2 & 1;
                    *(float2*)&dstbase[(((size_t)(b_ * HH + h) * SQ + s_) * DD) + d] =
                        make_float2(v10, v11);
                }
            }
        }
    }
}

// ---------------------------------------------------------------------------
// Banded attention, no-max softmax (scores bounded: q pre-scaled by 1/sqrt(D),
// softmax is shift-invariant, exp can't overflow fp32 here).
// grid = (S/128, B*H), block = 128 (1 thread = 1 query row).
// Exact band bounds: tile t-1 -> j in [tid,128); t -> all; t+1 -> j in [0,tid).
// Loop bounds are warp-uniform; lane masking handles the ragged edge.
// Dynamic smem 64KB -> 3 blocks/SM.
// ---------------------------------------------------------------------------
__global__ __launch_bounds__(128) void attn_kernel()
{
    extern __shared__ float smf[];
    float* Ks = smf;                  // [128][64]
    float* Vs = smf + 128 * 64;       // [128][64]

    const int t   = blockIdx.x;
    const int bh  = blockIdx.y;
    const int tid = threadIdx.x;
    const int wid = tid >> 5;
    const int i   = t * 128 + tid;

    const float* __restrict__ qrow = g_q + ((size_t)bh * SQ + i) * DD;
    float q[DD];
#pragma unroll
    for (int u = 0; u < DD / 4; u++)
        *reinterpret_cast<float4*>(&q[u * 4]) =
            *reinterpret_cast<const float4*>(&qrow[u * 4]);

    float l_run = 0.0f;
    float acc[DD];
#pragma unroll
    for (int d = 0; d < DD; d++) acc[d] = 0.0f;

#pragma unroll 1
    for (int dt = -1; dt <= 1; dt++) {
        const int kt = t + dt;
        if (kt < 0 || kt >= SQ / 128) continue;

        __syncthreads();
        const float* __restrict__ kbase = g_k + ((size_t)bh * SQ + kt * 128) * DD;
        const float* __restrict__ vbase = g_v + ((size_t)bh * SQ + kt * 128) * DD;
#pragma unroll
        for (int u = 0; u < 16; u++) {
            int idx = tid + u * 128;
            *reinterpret_cast<float4*>(&Ks[idx * 4]) =
                *reinterpret_cast<const float4*>(&kbase[idx * 4]);
            *reinterpret_cast<float4*>(&Vs[idx * 4]) =
                *reinterpret_cast<const float4*>(&vbase[idx * 4]);
        }
        __syncthreads();

        // Warp-uniform j range; per-lane mask only on the ragged 32.
        int jlo, jhi;
        bool mask_lo = false, mask_hi = false;
        if (dt == -1)      { jlo = wid * 32;  jhi = 128;          mask_lo = true; }
        else if (dt == 0)  { jlo = 0;         jhi = 128; }
        else               { jlo = 0;         jhi = wid * 32 + 32; mask_hi = true; }

#pragma unroll 1
        for (int j = jlo; j < jhi; j++) {
            const float* __restrict__ kr = &Ks[j * DD];
            float d0 = 0.f, d1 = 0.f, d2 = 0.f, d3 = 0.f;
#pragma unroll
            for (int d = 0; d < DD; d += 4) {
                float4 kv = *reinterpret_cast<const float4*>(&kr[d]);
                d0 = fmaf(q[d + 0], kv.x, d0);
                d1 = fmaf(q[d + 1], kv.y, d1);
                d2 = fmaf(q[d + 2], kv.z, d2);
                d3 = fmaf(q[d + 3], kv.w, d3);
            }
            float dot = (d0 + d1) + (d2 + d3);
            bool ok = true;
            if (mask_lo) ok = (j >= tid);
            if (mask_hi) ok = (j < tid);
            float p = ok ? __expf(dot) : 0.0f;
            l_run += p;
            const float* __restrict__ vr = &Vs[j * DD];
#pragma unroll
            for (int d = 0; d < DD; d += 4) {
                float4 vv = *reinterpret_cast<const float4*>(&vr[d]);
                acc[d + 0] = fmaf(p, vv.x, acc[d + 0]);
                acc[d + 1] = fmaf(p, vv.y, acc[d + 1]);
                acc[d + 2] = fmaf(p, vv.z, acc[d + 2]);
                acc[d + 3] = fmaf(p, vv.w, acc[d + 3]);
            }
        }
    }

    const float inv = 1.0f / l_run;
    const int b = bh >> 4;
    const int h = bh & 15;
    float* __restrict__ crow = g_ctx + ((size_t)i * BB + b) * EE + h * DD;
#pragma unroll
    for (int u = 0; u < DD / 4; u++) {
        float4 o;
        o.x = acc[u * 4 + 0] * inv;
        o.y = acc[u * 4 + 1] * inv;
        o.z = acc[u * 4 + 2] * inv;
        o.w = acc[u * 4 + 3] * inv;
        *reinterpret_cast<float4*>(&crow[u * 4]) = o;
    }
}

// ---------------------------------------------------------------------------
extern "C" void kernel_launch(void* const* d_in, const int* in_sizes, int n_in,
                              void* d_out, int out_size)
{
    const float* q_in  = (const float*)d_in[0];
    const float* k_in  = (const float*)d_in[1];
    const float* v_in  = (const float*)d_in[2];
    const float* w_in  = (const float*)d_in[3];
    const float* b_in  = (const float*)d_in[4];
    const float* w_out = (const float*)d_in[5];
    const float* b_out = (const float*)d_in[6];
    float* out = (float*)d_out;

    void *p_ah, *p_al, *p_wh, *p_wl, *p_ch, *p_cl, *p_woh, *p_wol, *p_ctx;
    cudaGetSymbolAddress(&p_ah, g_ah);   cudaGetSymbolAddress(&p_al, g_al);
    cudaGetSymbolAddress(&p_wh, g_wh);   cudaGetSymbolAddress(&p_wl, g_wl);
    cudaGetSymbolAddress(&p_ch, g_ch);   cudaGetSymbolAddress(&p_cl, g_cl);
    cudaGetSymbolAddress(&p_woh, g_woh); cudaGetSymbolAddress(&p_wol, g_wol);
    cudaGetSymbolAddress(&p_ctx, g_ctx);

    const int nA4  = (MM * EE) / 4;
    const int nW4  = (3 * EE * EE) / 4;
    const int nWo4 = (EE * EE) / 4;
    const size_t Abytes = (size_t)MM * EE;   // halfs per slice

    // Split-precision conversions
    cvt_kernel<<<nA4 / 256, 256>>>((const float4*)q_in,
        (uint2*)((char*)p_ah + 0), (uint2*)((char*)p_al + 0), nA4);
    cvt_kernel<<<nA4 / 256, 256>>>((const float4*)k_in,
        (uint2*)((char*)p_ah + 2 * Abytes), (uint2*)((char*)p_al + 2 * Abytes), nA4);
    cvt_kernel<<<nA4 / 256, 256>>>((const float4*)v_in,
        (uint2*)((char*)p_ah + 4 * Abytes), (uint2*)((char*)p_al + 4 * Abytes), nA4);
    cvt_kernel<<<nW4 / 256, 256>>>((const float4*)w_in, (uint2*)p_wh, (uint2*)p_wl, nW4);
    cvt_kernel<<<nWo4 / 256, 256>>>((const float4*)w_out, (uint2*)p_woh, (uint2*)p_wol, nWo4);

    // QKV projection (grid 32 x 24)
    const int gemm_smem = 2 * 4 * 128 * LDSTRIDE * 2;   // 81920
    cudaFuncSetAttribute(mma_gemm_kernel, cudaFuncAttributeMaxDynamicSharedMemorySize, gemm_smem);
    mma_gemm_kernel<<<dim3(MM / 128, (3 * EE) / 128), 256, gemm_smem>>>(
        (const __nv_bfloat16*)p_ah, (const __nv_bfloat16*)p_al,
        (const __nv_bfloat16*)p_wh, (const __nv_bfloat16*)p_wl,
        b_in, 0, nullptr);

    // Banded attention
    const int attn_smem = 2 * 128 * 64 * 4;             // 65536
    cudaFuncSetAttribute(attn_kernel, cudaFuncAttributeMaxDynamicSharedMemorySize, attn_smem);
    attn_kernel<<<dim3(SQ / 128, BB * HH), 128, attn_smem>>>();

    // ctx -> bf16 split, then out projection (grid 32 x 8)
    cvt_kernel<<<nA4 / 256, 256>>>((const float4*)p_ctx, (uint2*)p_ch, (uint2*)p_cl, nA4);
    mma_gemm_kernel<<<dim3(MM / 128, EE / 128), 256, gemm_smem>>>(
        (const __nv_bfloat16*)p_ch, (const __nv_bfloat16*)p_cl,
        (const __nv_bfloat16*)p_woh, (const __nv_bfloat16*)p_wol,
        b_out, 1, out);
}

// round 4
// speedup vs baseline: 3.6842x; 1.8103x over previous
#include <cuda_runtime.h>
#include <cstdint>

// Problem constants
#define SQ   2048
#define BB   2
#define EE   1024
#define HH   16
#define DD   64
#define MM   (SQ * BB)
#define BK   32
#define NSTAGE (EE / BK)        // 32
#define ASTRIDE 36              // floats per smem row in GEMM tiles (conflict-free)

// Attention smem strides (floats) — chosen so mma frag LDS is conflict-free
#define QS 68
#define VS 72
#define PS 132

// ---------------------------------------------------------------------------
// Scratch (device globals — no allocation allowed)
// ---------------------------------------------------------------------------
__device__ float g_q[BB * HH * SQ * DD];    // [B,H,S,D], tf32-rounded, prescaled 1/8
__device__ float g_k[BB * HH * SQ * DD];    // tf32-rounded
__device__ float g_v[BB * HH * SQ * DD];    // tf32-rounded
__device__ float g_ctx[SQ * BB * EE];       // [S,B,E]

// ---------------------------------------------------------------------------
// PTX helpers (sm_80+ portable — harness targets plain sm_103)
// ---------------------------------------------------------------------------
__device__ __forceinline__ uint32_t smem_u32(const void* p) {
    uint32_t a;
    asm("{ .reg .u64 t; cvta.to.shared.u64 t, %1; cvt.u32.u64 %0, t; }"
        : "=r"(a) : "l"(p));
    return a;
}

#define CP_ASYNC16(saddr, gaddr) \
    asm volatile("cp.async.cg.shared.global [%0], [%1], 16;" \
                 :: "r"(saddr), "l"(gaddr) : "memory")
#define CP_COMMIT() asm volatile("cp.async.commit_group;" ::: "memory")
#define CP_WAIT(n)  asm volatile("cp.async.wait_group %0;" :: "n"(n) : "memory")

// fp32 -> tf32 (round-to-nearest) producing b32 operand
__device__ __forceinline__ uint32_t f2t(float x) {
    uint32_t r;
    asm("cvt.rna.tf32.f32 %0, %1;" : "=r"(r) : "f"(x));
    return r;
}
// fp32 -> tf32-rounded fp32 value (for pre-rounding stores)
__device__ __forceinline__ float round_tf32(float x) {
    uint32_t r;
    asm("cvt.rna.tf32.f32 %0, %1;" : "=r"(r) : "f"(x));
    return __uint_as_float(r);
}

__device__ __forceinline__ void mma_tf32(float* d, const uint32_t* a, const uint32_t* b) {
    asm volatile("mma.sync.aligned.m16n8k8.row.col.f32.tf32.tf32.f32 "
                 "{%0,%1,%2,%3}, {%4,%5,%6,%7}, {%8,%9}, {%0,%1,%2,%3};"
                 : "+f"(d[0]), "+f"(d[1]), "+f"(d[2]), "+f"(d[3])
                 : "r"(a[0]), "r"(a[1]), "r"(a[2]), "r"(a[3]), "r"(b[0]), "r"(b[1]));
}

// ---------------------------------------------------------------------------
// tf32 GEMM: C[m][n] = A[m][:] . W[n][:] + bias[n]  (single pass)
// Tile 128x128, BK=32, cp.async double buffer, 8 warps (2M x 4N of 64x32).
//   mode 0: A selected by which = n0>>10 (q/k/v inputs); scatter to
//           g_q/g_k/g_v [B,H,S,D] with q scaled 1/8; outputs tf32-rounded.
//   mode 1: A = first pointer (g_ctx); write outp [M, E] exact fp32.
// smem: 2 stages x (A,B) x 128 x ASTRIDE floats = 73728 B.
// ---------------------------------------------------------------------------
__global__ __launch_bounds__(256) void mma_gemm_kernel(
    const float* __restrict__ a0p, const float* __restrict__ a1p,
    const float* __restrict__ a2p, const float* __restrict__ w,
    const float* __restrict__ bias, int mode, float* __restrict__ outp)
{
    extern __shared__ __align__(16) float smf[];
    const uint32_t sb = smem_u32(smf);
    const int tid  = threadIdx.x;
    const int wid  = tid >> 5;
    const int lane = tid & 31;
    const int g    = lane >> 2;
    const int tg   = lane & 3;
    const int m0 = blockIdx.x * 128;
    const int n0 = blockIdx.y * 128;

    int which = 0;
    const float* __restrict__ A = a0p;
    if (mode == 0) {
        which = n0 >> 10;
        A = (which == 0) ? a0p : (which == 1) ? a1p : a2p;
    }

    const int warp_m = (wid & 1) * 64;
    const int warp_n = (wid >> 1) * 32;

    float acc[4][4][4];
#pragma unroll
    for (int mi = 0; mi < 4; mi++)
#pragma unroll
        for (int ni = 0; ni < 4; ni++)
#pragma unroll
            for (int r = 0; r < 4; r++) acc[mi][ni][r] = 0.0f;

    // Stage buffer (bytes): A at base, B at base + 18432; stage stride 36864.
    auto issue_stage = [&](int s) {
        const int k0 = s * BK;
        const uint32_t base = sb + (uint32_t)(s & 1) * 36864u;
#pragma unroll
        for (int u = 0; u < 4; u++) {
            int ch  = tid + u * 256;       // 0..1023
            int row = ch >> 3;
            int c16 = ch & 7;
            uint32_t so = (uint32_t)row * 144u + (uint32_t)c16 * 16u;
            CP_ASYNC16(base + so,           A + (size_t)(m0 + row) * EE + k0 + c16 * 4);
            CP_ASYNC16(base + 18432u + so,  w + (size_t)(n0 + row) * EE + k0 + c16 * 4);
        }
        CP_COMMIT();
    };

    issue_stage(0);

    for (int s = 0; s < NSTAGE; s++) {
        if (s + 1 < NSTAGE) { issue_stage(s + 1); CP_WAIT(1); }
        else                { CP_WAIT(0); }
        __syncthreads();

        const float* As = smf + (s & 1) * 9216;
        const float* Bs = As + 4608;
#pragma unroll
        for (int ks = 0; ks < 4; ks++) {
            uint32_t af[4][4], bf[4][2];
#pragma unroll
            for (int mi = 0; mi < 4; mi++) {
                const float* p = As + (warp_m + mi * 16 + g) * ASTRIDE + ks * 8 + tg;
                af[mi][0] = f2t(p[0]);
                af[mi][1] = f2t(p[8 * ASTRIDE]);
                af[mi][2] = f2t(p[4]);
                af[mi][3] = f2t(p[8 * ASTRIDE + 4]);
            }
#pragma unroll
            for (int ni = 0; ni < 4; ni++) {
                const float* p = Bs + (warp_n + ni * 8 + g) * ASTRIDE + ks * 8 + tg;
                bf[ni][0] = f2t(p[0]);
                bf[ni][1] = f2t(p[4]);
            }
#pragma unroll
            for (int mi = 0; mi < 4; mi++)
#pragma unroll
                for (int ni = 0; ni < 4; ni++)
                    mma_tf32(acc[mi][ni], af[mi], bf[ni]);
        }
        __syncthreads();
    }

    // Epilogue
    const float scale = (mode == 0 && which == 0) ? 0.125f : 1.0f;
    float* dstbase = nullptr;
    if (mode == 0) dstbase = (which == 0) ? g_q : (which == 1) ? g_k : g_v;

#pragma unroll
    for (int mi = 0; mi < 4; mi++) {
        const int m1 = m0 + warp_m + mi * 16 + g;
        const int m2 = m1 + 8;
#pragma unroll
        for (int ni = 0; ni < 4; ni++) {
            const int n = n0 + warp_n + ni * 8 + tg * 2;
            const float b0 = bias[n], b1 = bias[n + 1];
            float v00 = (acc[mi][ni][0] + b0) * scale;
            float v01 = (acc[mi][ni][1] + b1) * scale;
            float v10 = (acc[mi][ni][2] + b0) * scale;
            float v11 = (acc[mi][ni][3] + b1) * scale;
            if (mode == 1) {
                *(float2*)&outp[(size_t)m1 * EE + n] = make_float2(v00, v01);
                *(float2*)&outp[(size_t)m2 * EE + n] = make_float2(v10, v11);
            } else {
                // pre-round to tf32 so attention skips in-loop cvt for Q/K/V
                v00 = round_tf32(v00); v01 = round_tf32(v01);
                v10 = round_tf32(v10); v11 = round_tf32(v11);
                const int nl = n & 1023;
                const int h  = nl >> 6;
                const int d  = nl & 63;
                {
                    const int s_ = m1 >> 1, b_ = m1 & 1;
                    *(float2*)&dstbase[(((size_t)(b_ * HH + h) * SQ + s_) * DD) + d] =
                        make_float2(v00, v01);
                }
                {
                    const int s_ = m2 >> 1, b_ = m2 & 1;
                    *(float2*)&dstbase[(((size_t)(b_ * HH + h) * SQ + s_) * DD) + d] =
                        make_float2(v10, v11);
                }
            }
        }
    }
}

// ---------------------------------------------------------------------------
// Banded flash attention on tf32 mma.sync.
// grid = (S/128 = 16, B*H = 32), block = 256 (8 warps; warp w owns 16 query
// rows w*16..w*16+15 of the 128-query tile).
// Per key tile kt in {t-1, t, t+1}: S = Q.K^T via mma (band-skipped n-frags),
// p = exp(s) masked (no max shift: scores bounded, softmax shift-invariant),
// P staged in smem, O += P.V via mma (matching k-frag skip). Per-warp P rows
// -> only __syncwarp between QK and PV.
// smem (bytes): Q 34816 | K 34816 | V 36864 | P 67584  = 174080.
// ---------------------------------------------------------------------------
__global__ __launch_bounds__(256) void attn_kernel()
{
    extern __shared__ __align__(16) float smf[];
    const uint32_t sb = smem_u32(smf);
    float* Qs = smf;                 // [128][QS]
    float* Ks = smf + 8704;          // [128][QS]
    float* Vs = smf + 17408;         // [128][VS]
    float* Ps = smf + 26624;         // [128][PS]

    const int t   = blockIdx.x;
    const int bh  = blockIdx.y;
    const int tid = threadIdx.x;
    const int w   = tid >> 5;
    const int lane = tid & 31;
    const int g   = lane >> 2;
    const int tg  = lane & 3;

    // Load Q tile (stays resident all tiles)
    {
        const float* qbase = g_q + ((size_t)bh * SQ + t * 128) * DD;
#pragma unroll
        for (int u = 0; u < 8; u++) {
            int ch = tid + u * 256;            // 0..2047
            int row = ch >> 4, c = ch & 15;
            CP_ASYNC16(sb + (uint32_t)row * 272u + (uint32_t)c * 16u,
                       qbase + row * DD + c * 4);
        }
        CP_COMMIT();
    }

    float l0 = 0.f, l1 = 0.f;
    float O[8][4];
#pragma unroll
    for (int nf = 0; nf < 8; nf++)
#pragma unroll
        for (int r = 0; r < 4; r++) O[nf][r] = 0.f;

    uint32_t qf[8][4];
    bool qloaded = false;

    const int kt0 = (t > 0) ? t - 1 : t;
    const int kt1 = (t < SQ / 128 - 1) ? t + 1 : t;

#pragma unroll 1
    for (int kt = kt0; kt <= kt1; kt++) {
        __syncthreads();   // prior tile's K/V reads complete before overwrite
        {
            const float* kbase = g_k + ((size_t)bh * SQ + kt * 128) * DD;
            const float* vbase = g_v + ((size_t)bh * SQ + kt * 128) * DD;
#pragma unroll
            for (int u = 0; u < 8; u++) {
                int ch = tid + u * 256;
                int row = ch >> 4, c = ch & 15;
                CP_ASYNC16(sb + 34816u + (uint32_t)row * 272u + (uint32_t)c * 16u,
                           kbase + row * DD + c * 4);
                CP_ASYNC16(sb + 69632u + (uint32_t)row * 288u + (uint32_t)c * 16u,
                           vbase + row * DD + c * 4);
            }
            CP_COMMIT();
        }
        CP_WAIT(0);
        __syncthreads();

        if (!qloaded) {
            qloaded = true;
#pragma unroll
            for (int ks = 0; ks < 8; ks++) {
                const float* p = Qs + (w * 16 + g) * QS + ks * 8 + tg;
                qf[ks][0] = __float_as_uint(p[0]);
                qf[ks][1] = __float_as_uint(p[8 * QS]);
                qf[ks][2] = __float_as_uint(p[4]);
                qf[ks][3] = __float_as_uint(p[8 * QS + 4]);
            }
        }

        const int dt = kt - t;
        const int niLo = (dt < 0) ? 2 * w : 0;
        const int niHi = (dt > 0) ? 2 * w + 2 : 16;
        const int r0 = w * 16 + g;
        const int r1 = r0 + 8;

#pragma unroll 1
        for (int ni = niLo; ni < niHi; ni++) {
            float c[4] = {0.f, 0.f, 0.f, 0.f};
#pragma unroll
            for (int ks = 0; ks < 8; ks++) {
                uint32_t b[2];
                const float* kp = Ks + (ni * 8 + g) * QS + ks * 8 + tg;
                b[0] = __float_as_uint(kp[0]);
                b[1] = __float_as_uint(kp[4]);
                mma_tf32(c, qf[ks], b);
            }
            const int col0 = ni * 8 + 2 * tg;
            float p0, p1, p2, p3;
            if (dt < 0) {
                p0 = (col0     >= r0) ? __expf(c[0]) : 0.f;
                p1 = (col0 + 1 >= r0) ? __expf(c[1]) : 0.f;
                p2 = (col0     >= r1) ? __expf(c[2]) : 0.f;
                p3 = (col0 + 1 >= r1) ? __expf(c[3]) : 0.f;
            } else if (dt > 0) {
                p0 = (col0     < r0) ? __expf(c[0]) : 0.f;
                p1 = (col0 + 1 < r0) ? __expf(c[1]) : 0.f;
                p2 = (col0     < r1) ? __expf(c[2]) : 0.f;
                p3 = (col0 + 1 < r1) ? __expf(c[3]) : 0.f;
            } else {
                p0 = __expf(c[0]); p1 = __expf(c[1]);
                p2 = __expf(c[2]); p3 = __expf(c[3]);
            }
            l0 += p0 + p1;
            l1 += p2 + p3;
            *(float2*)&Ps[r0 * PS + col0] = make_float2(p0, p1);
            *(float2*)&Ps[r1 * PS + col0] = make_float2(p2, p3);
        }
        __syncwarp();

        const int ksLo = (dt < 0) ? 2 * w : 0;
        const int ksHi = (dt > 0) ? 2 * w + 2 : 16;
#pragma unroll 1
        for (int ks = ksLo; ks < ksHi; ks++) {
            uint32_t a[4];
            const float* pp = Ps + (w * 16 + g) * PS + ks * 8 + tg;
            a[0] = f2t(pp[0]);
            a[1] = f2t(pp[8 * PS]);
            a[2] = f2t(pp[4]);
            a[3] = f2t(pp[8 * PS + 4]);
#pragma unroll
            for (int nf = 0; nf < 8; nf++) {
                uint32_t b[2];
                const float* vp = Vs + (ks * 8 + tg) * VS + nf * 8 + g;
                b[0] = __float_as_uint(vp[0]);
                b[1] = __float_as_uint(vp[4 * VS]);
                mma_tf32(O[nf], a, b);
            }
        }
    }

    // Row-sum reduction across the quad (lanes sharing g)
    l0 += __shfl_xor_sync(0xffffffff, l0, 1);
    l0 += __shfl_xor_sync(0xffffffff, l0, 2);
    l1 += __shfl_xor_sync(0xffffffff, l1, 1);
    l1 += __shfl_xor_sync(0xffffffff, l1, 2);
    const float inv0 = 1.0f / l0;
    const float inv1 = 1.0f / l1;

    const int b_ = bh >> 4;
    const int h_ = bh & 15;
    const int i0 = t * 128 + w * 16 + g;
    const int i1 = i0 + 8;
#pragma unroll
    for (int nf = 0; nf < 8; nf++) {
        const int d = h_ * 64 + nf * 8 + 2 * tg;
        *(float2*)&g_ctx[((size_t)i0 * BB + b_) * EE + d] =
            make_float2(O[nf][0] * inv0, O[nf][1] * inv0);
        *(float2*)&g_ctx[((size_t)i1 * BB + b_) * EE + d] =
            make_float2(O[nf][2] * inv1, O[nf][3] * inv1);
    }
}

// ---------------------------------------------------------------------------
extern "C" void kernel_launch(void* const* d_in, const int* in_sizes, int n_in,
                              void* d_out, int out_size)
{
    const float* q_in  = (const float*)d_in[0];
    const float* k_in  = (const float*)d_in[1];
    const float* v_in  = (const float*)d_in[2];
    const float* w_in  = (const float*)d_in[3];
    const float* b_in  = (const float*)d_in[4];
    const float* w_out = (const float*)d_in[5];
    const float* b_out = (const float*)d_in[6];
    float* out = (float*)d_out;

    void* p_ctx;
    cudaGetSymbolAddress(&p_ctx, g_ctx);

    const int gemm_smem = 2 * 2 * 128 * ASTRIDE * 4;   // 73728
    cudaFuncSetAttribute(mma_gemm_kernel, cudaFuncAttributeMaxDynamicSharedMemorySize, gemm_smem);

    // QKV projection (grid 32 x 24)
    mma_gemm_kernel<<<dim3(MM / 128, (3 * EE) / 128), 256, gemm_smem>>>(
        q_in, k_in, v_in, w_in, b_in, 0, nullptr);

    // Banded attention on tensor pipe
    const int attn_smem = 174080;
    cudaFuncSetAttribute(attn_kernel, cudaFuncAttributeMaxDynamicSharedMemorySize, attn_smem);
    attn_kernel<<<dim3(SQ / 128, BB * HH), 256, attn_smem>>>();

    // Output projection (grid 32 x 8)
    mma_gemm_kernel<<<dim3(MM / 128, EE / 128), 256, gemm_smem>>>(
        (const float*)p_ctx, nullptr, nullptr, w_out, b_out, 1, out);
}